// round 6
// baseline (speedup 1.0000x reference)
#include <cuda_runtime.h>
#include <math.h>

#define BATCH 4

// Scratch (no cudaMalloc allowed). Sized for the largest consumers:
//  h1: max over stages of U*B*64*H*W = stage x8 (4*4*64*256*256)
//                                    = msf stage (1*4*64*512*512) = 67,108,864 floats
//  h2: 32 channels -> half of that
__device__ float g_h1[67108864];
__device__ float g_h2[33554432];
__device__ float g_msf[BATCH * 512 * 512];

// ---------------------------------------------------------------------------
// conv1: 1 -> 64 channels, 9x9, SAME pad(4), ReLU.  Input (B,1,H,W) shared by
// all U units of a stage. Output g_h1[(u*B+b)*64 + oc][H][W].
// Block 16x16 threads, each thread computes 4 adjacent columns (tile 64x16).
// ---------------------------------------------------------------------------
__global__ __launch_bounds__(256) void conv1_kernel(
    const float* __restrict__ in, int use_msf,
    const float* __restrict__ Wp,   // stage base: (U,64,9,9)
    const float* __restrict__ Bp,   // stage base: (U,64)
    int H, int W)
{
    __shared__ float s_in[24][72];
    __shared__ float s_w[64 * 81];
    __shared__ float s_b[64];

    int z = blockIdx.z;             // u*BATCH + b
    int u = z / BATCH, b = z % BATCH;
    int tid = threadIdx.y * 16 + threadIdx.x;

    const float* wu = Wp + (size_t)u * 64 * 81;
    for (int i = tid; i < 64 * 81; i += 256) s_w[i] = wu[i];
    if (tid < 64) s_b[tid] = Bp[u * 64 + tid];

    const float* src = use_msf ? g_msf : in;
    const float* inb = src + (size_t)b * H * W;
    int ty0 = blockIdx.y * 16 - 4;
    int tx0 = blockIdx.x * 64 - 4;
    for (int i = tid; i < 24 * 72; i += 256) {
        int r = i / 72, c = i % 72;
        int gy = ty0 + r, gx = tx0 + c;
        s_in[r][c] = (gy >= 0 && gy < H && gx >= 0 && gx < W) ? inb[gy * W + gx] : 0.f;
    }
    __syncthreads();

    int oy  = blockIdx.y * 16 + threadIdx.y;
    int ox0 = blockIdx.x * 64 + threadIdx.x * 4;

    float* outb = g_h1 + (((size_t)z * 64) * H + oy) * W + ox0;
    for (int oc = 0; oc < 64; oc++) {
        const float* wr = &s_w[oc * 81];
        float a0, a1, a2, a3;
        a0 = a1 = a2 = a3 = s_b[oc];
#pragma unroll
        for (int ky = 0; ky < 9; ky++) {
            float r[12];
#pragma unroll
            for (int j = 0; j < 12; j++)
                r[j] = s_in[threadIdx.y + ky][threadIdx.x * 4 + j];
#pragma unroll
            for (int kx = 0; kx < 9; kx++) {
                float w = wr[ky * 9 + kx];
                a0 = fmaf(r[kx], w, a0);
                a1 = fmaf(r[kx + 1], w, a1);
                a2 = fmaf(r[kx + 2], w, a2);
                a3 = fmaf(r[kx + 3], w, a3);
            }
        }
        float4 v = make_float4(fmaxf(a0, 0.f), fmaxf(a1, 0.f),
                               fmaxf(a2, 0.f), fmaxf(a3, 0.f));
        *reinterpret_cast<float4*>(outb + (size_t)oc * H * W) = v;
    }
}

// ---------------------------------------------------------------------------
// conv2: 64 -> 32 channels, 5x5, SAME pad(2), ReLU. 2x2 micro-tile, 16 oc per
// block (grid.z = (u*B+b)*2 + ocGroup). FMA-bound by design (~1600 FMA vs
// ~460 LDS per ic per thread).
// ---------------------------------------------------------------------------
__global__ __launch_bounds__(256) void conv2_kernel(
    const float* __restrict__ Wp,   // stage base: (U,32,64,5,5)
    const float* __restrict__ Bp,   // stage base: (U,32)
    int H, int W)
{
    __shared__ float s_in[36][36];
    __shared__ float s_w[16 * 25];

    int z   = blockIdx.z;
    int g   = z & 1;
    int ub  = z >> 1;               // u*BATCH + b
    int u   = ub / BATCH;
    int oc0 = g * 16;
    int tid = threadIdx.y * 16 + threadIdx.x;

    const float* wbase = Wp + (((size_t)u * 32 + oc0) * 64) * 25;

    float acc[16][2][2];
#pragma unroll
    for (int oc = 0; oc < 16; oc++) {
        float bv = Bp[u * 32 + oc0 + oc];
        acc[oc][0][0] = bv; acc[oc][0][1] = bv;
        acc[oc][1][0] = bv; acc[oc][1][1] = bv;
    }

    int ty0 = blockIdx.y * 32 - 2, tx0 = blockIdx.x * 32 - 2;
    const float* h1b = g_h1 + ((size_t)ub * 64) * H * W;
    int iy = threadIdx.y * 2, ix = threadIdx.x * 2;

    for (int ic = 0; ic < 64; ic++) {
        __syncthreads();
        const float* inc = h1b + (size_t)ic * H * W;
        for (int i = tid; i < 36 * 36; i += 256) {
            int r = i / 36, c = i % 36;
            int gy = ty0 + r, gx = tx0 + c;
            s_in[r][c] = (gy >= 0 && gy < H && gx >= 0 && gx < W) ? inc[gy * W + gx] : 0.f;
        }
        for (int i = tid; i < 400; i += 256) {
            int oc = i / 25, k = i % 25;
            s_w[i] = wbase[((size_t)oc * 64 + ic) * 25 + k];
        }
        __syncthreads();

#pragma unroll 1
        for (int ky = 0; ky < 5; ky++) {
            float rA[6], rB[6];
#pragma unroll
            for (int j = 0; j < 6; j++) {
                rA[j] = s_in[iy + ky][ix + j];
                rB[j] = s_in[iy + ky + 1][ix + j];
            }
#pragma unroll
            for (int oc = 0; oc < 16; oc++) {
#pragma unroll
                for (int kx = 0; kx < 5; kx++) {
                    float w = s_w[oc * 25 + ky * 5 + kx];
                    acc[oc][0][0] = fmaf(rA[kx],     w, acc[oc][0][0]);
                    acc[oc][0][1] = fmaf(rA[kx + 1], w, acc[oc][0][1]);
                    acc[oc][1][0] = fmaf(rB[kx],     w, acc[oc][1][0]);
                    acc[oc][1][1] = fmaf(rB[kx + 1], w, acc[oc][1][1]);
                }
            }
        }
    }

    int oy = blockIdx.y * 32 + iy, ox = blockIdx.x * 32 + ix;
    float* h2b = g_h2 + ((size_t)ub * 32 + oc0) * H * W;
#pragma unroll
    for (int oc = 0; oc < 16; oc++) {
        float* p = h2b + (size_t)oc * H * W + (size_t)oy * W + ox;
        p[0]     = fmaxf(acc[oc][0][0], 0.f);
        p[1]     = fmaxf(acc[oc][0][1], 0.f);
        p[W]     = fmaxf(acc[oc][1][0], 0.f);
        p[W + 1] = fmaxf(acc[oc][1][1], 0.f);
    }
}

// ---------------------------------------------------------------------------
// conv3: 32 -> 1 channel, 5x5, SAME pad(2), no ReLU. Writes directly into
// the (optionally 2x-interleaved) output section.
// ---------------------------------------------------------------------------
__global__ __launch_bounds__(256) void conv3_kernel(
    const float* __restrict__ Wp,   // stage base: (U,1,32,5,5)
    const float* __restrict__ Bp,   // stage base: (U,)
    float* __restrict__ outsec,
    int H, int W, int interleave)
{
    __shared__ float s_in[36][36];
    __shared__ float s_w[25];

    int z = blockIdx.z;             // u*BATCH + b
    int u = z / BATCH, b = z % BATCH;
    int tid = threadIdx.y * 16 + threadIdx.x;

    const float* wbase = Wp + (size_t)u * 32 * 25;
    float bv = Bp[u];
    float a00 = bv, a01 = bv, a10 = bv, a11 = bv;

    int ty0 = blockIdx.y * 32 - 2, tx0 = blockIdx.x * 32 - 2;
    const float* h2b = g_h2 + ((size_t)z * 32) * H * W;
    int iy = threadIdx.y * 2, ix = threadIdx.x * 2;

    for (int ic = 0; ic < 32; ic++) {
        __syncthreads();
        const float* inc = h2b + (size_t)ic * H * W;
        for (int i = tid; i < 36 * 36; i += 256) {
            int r = i / 36, c = i % 36;
            int gy = ty0 + r, gx = tx0 + c;
            s_in[r][c] = (gy >= 0 && gy < H && gx >= 0 && gx < W) ? inc[gy * W + gx] : 0.f;
        }
        if (tid < 25) s_w[tid] = wbase[ic * 25 + tid];
        __syncthreads();

#pragma unroll
        for (int ky = 0; ky < 5; ky++) {
            float rA[6], rB[6];
#pragma unroll
            for (int j = 0; j < 6; j++) {
                rA[j] = s_in[iy + ky][ix + j];
                rB[j] = s_in[iy + ky + 1][ix + j];
            }
#pragma unroll
            for (int kx = 0; kx < 5; kx++) {
                float w = s_w[ky * 5 + kx];
                a00 = fmaf(rA[kx],     w, a00);
                a01 = fmaf(rA[kx + 1], w, a01);
                a10 = fmaf(rB[kx],     w, a10);
                a11 = fmaf(rB[kx + 1], w, a11);
            }
        }
    }

    int oy = blockIdx.y * 32 + iy, ox = blockIdx.x * 32 + ix;
    int s  = interleave ? 2 : 1;
    int ry = interleave ? (u >> 1) : 0;
    int rx = interleave ? (u & 1) : 0;
    int OW = s * W, OH = s * H;
    float* ob = outsec + (size_t)b * OH * OW;
    ob[(size_t)(s * oy + ry)       * OW + s * ox       + rx] = a00;
    ob[(size_t)(s * oy + ry)       * OW + s * (ox + 1) + rx] = a01;
    ob[(size_t)(s * (oy + 1) + ry) * OW + s * ox       + rx] = a10;
    ob[(size_t)(s * (oy + 1) + ry) * OW + s * (ox + 1) + rx] = a11;
}

// ---------------------------------------------------------------------------
// msf_in = bilinear_up4(out_x2) + bilinear_up2(out_x4) + out_x8
// jax.image.resize('bilinear') half-pixel sampling; edge renormalization is
// equivalent to clamping the two sample indices.
// ---------------------------------------------------------------------------
__device__ __forceinline__ float bil_up(const float* img, int N, int sc, int y, int x)
{
    float fy = (y + 0.5f) / sc - 0.5f;
    float fx = (x + 0.5f) / sc - 0.5f;
    int y0 = (int)floorf(fy); float wy = fy - y0;
    int x0 = (int)floorf(fx); float wx = fx - x0;
    int y0c = y0 < 0 ? 0 : y0;        int y1c = y0 + 1 > N - 1 ? N - 1 : y0 + 1;
    int x0c = x0 < 0 ? 0 : x0;        int x1c = x0 + 1 > N - 1 ? N - 1 : x0 + 1;
    float p00 = img[(size_t)y0c * N + x0c], p01 = img[(size_t)y0c * N + x1c];
    float p10 = img[(size_t)y1c * N + x0c], p11 = img[(size_t)y1c * N + x1c];
    return (1.f - wy) * ((1.f - wx) * p00 + wx * p01)
         +        wy  * ((1.f - wx) * p10 + wx * p11);
}

__global__ __launch_bounds__(256) void msf_in_kernel(const float* __restrict__ outbuf)
{
    int idx = blockIdx.x * blockDim.x + threadIdx.x;
    if (idx >= BATCH * 512 * 512) return;
    int x = idx & 511;
    int y = (idx >> 9) & 511;
    int b = idx >> 18;
    const float* x2 = outbuf + 0      + (size_t)b * 128 * 128;
    const float* x4 = outbuf + 65536  + (size_t)b * 256 * 256;
    const float* x8 = outbuf + 327680 + (size_t)b * 512 * 512;
    g_msf[idx] = bil_up(x2, 128, 4, y, x)
               + bil_up(x4, 256, 2, y, x)
               + x8[(size_t)y * 512 + x];
}

// ---------------------------------------------------------------------------
extern "C" void kernel_launch(void* const* d_in, const int* in_sizes, int n_in,
                              void* d_out, int out_size)
{
    const float* image = (const float*)d_in[0];
    const float* W1 = (const float*)d_in[1];
    const float* B1 = (const float*)d_in[2];
    const float* W2 = (const float*)d_in[3];
    const float* B2 = (const float*)d_in[4];
    const float* W3 = (const float*)d_in[5];
    const float* B3 = (const float*)d_in[6];
    float* out = (float*)d_out;

    // output sections: x2 (4,128,128) | x4 (4,256,256) | x8 (4,512,512) | msf (4,512,512)
    float* sec_x2  = out;
    float* sec_x4  = out + 65536;
    float* sec_x8  = out + 327680;
    float* sec_msf = out + 1376256;

    struct Stage { const float* in; int use_msf, H, W, ub, U, inter; float* osec; };
    Stage st[4] = {
        { image,   0,  64,  64,  0, 4, 1, sec_x2  },
        { sec_x2,  0, 128, 128,  4, 4, 1, sec_x4  },
        { sec_x4,  0, 256, 256,  8, 4, 1, sec_x8  },
        { nullptr, 1, 512, 512, 12, 1, 0, sec_msf },
    };

    dim3 blk(16, 16);
    for (int s = 0; s < 4; s++) {
        if (s == 3)
            msf_in_kernel<<<(BATCH * 512 * 512 + 255) / 256, 256>>>(out);
        Stage& t = st[s];
        conv1_kernel<<<dim3(t.W / 64, t.H / 16, t.U * BATCH), blk>>>(
            t.in, t.use_msf,
            W1 + (size_t)t.ub * 64 * 81, B1 + (size_t)t.ub * 64, t.H, t.W);
        conv2_kernel<<<dim3(t.W / 32, t.H / 32, t.U * BATCH * 2), blk>>>(
            W2 + (size_t)t.ub * 32 * 64 * 25, B2 + (size_t)t.ub * 32, t.H, t.W);
        conv3_kernel<<<dim3(t.W / 32, t.H / 32, t.U * BATCH), blk>>>(
            W3 + (size_t)t.ub * 32 * 25, B3 + t.ub, t.osec, t.H, t.W, t.inter);
    }
}

// round 10
// speedup vs baseline: 2.0143x; 2.0143x over previous
#include <cuda_runtime.h>
#include <cuda_fp16.h>
#include <math.h>
#include <stdint.h>

#define BATCH 4

__device__ float  g_h1 [67108864];   // conv1 out fp32 planar [ub][64][HW]
__device__ __half g_h1h[67108864];   // pixel-major fp16 hi [ub][HW][64]
__device__ __half g_h1l[67108864];   // pixel-major fp16 lo
__device__ float  g_h2 [33554432];   // conv2 out fp32 planar [ub][32][HW]
__device__ float  g_msf[BATCH * 512 * 512];

// ---------------- warp-MMA helpers (plain sm_103-safe PTX) ----------------
__device__ __forceinline__ uint32_t smem_u32(const void* p) {
    uint32_t a;
    asm("{ .reg .u64 t; cvta.to.shared.u64 t, %1; cvt.u32.u64 %0, t; }" : "=r"(a) : "l"(p));
    return a;
}
__device__ __forceinline__ void ldmat4(uint32_t* a, uint32_t addr) {
    asm volatile("ldmatrix.sync.aligned.m8n8.x4.shared.b16 {%0,%1,%2,%3}, [%4];"
        : "=r"(a[0]), "=r"(a[1]), "=r"(a[2]), "=r"(a[3]) : "r"(addr));
}
__device__ __forceinline__ void mma16816(float* c, const uint32_t* a,
                                         uint32_t b0, uint32_t b1) {
    asm volatile("mma.sync.aligned.m16n8k16.row.col.f32.f16.f16.f32 "
        "{%0,%1,%2,%3}, {%4,%5,%6,%7}, {%8,%9}, {%0,%1,%2,%3};"
        : "+f"(c[0]), "+f"(c[1]), "+f"(c[2]), "+f"(c[3])
        : "r"(a[0]), "r"(a[1]), "r"(a[2]), "r"(a[3]), "r"(b0), "r"(b1));
}

// conv2 SMEM layout (bytes). Pixel pitch 144 (conflict-free ldmatrix).
#define SLOT_B   9792            // 68 px * 144
#define A_HI     0
#define A_LO     58752           // 6 slots * 9792
#define B_OFF    117504
#define C2_SMEM  219904          // + 400 frags * 256B

// ---------------------------------------------------------------------------
// conv1: 1->64, 9x9, pad 4, ReLU. 16-oc register blocking.
// ---------------------------------------------------------------------------
__global__ __launch_bounds__(256) void conv1_kernel(
    const float* __restrict__ in, int use_msf,
    const float* __restrict__ Wp, const float* __restrict__ Bp,
    int H, int W)
{
    __shared__ float s_in[24][72];
    __shared__ float s_w[64 * 81];
    __shared__ float s_b[64];

    int z = blockIdx.z;
    int u = z / BATCH, b = z % BATCH;
    int tid = threadIdx.y * 16 + threadIdx.x;

    const float* wu = Wp + (size_t)u * 64 * 81;
    for (int i = tid; i < 64 * 81; i += 256) s_w[i] = wu[i];
    if (tid < 64) s_b[tid] = Bp[u * 64 + tid];

    const float* src = use_msf ? g_msf : in;
    const float* inb = src + (size_t)b * H * W;
    int ty0 = blockIdx.y * 16 - 4;
    int tx0 = blockIdx.x * 64 - 4;
    for (int i = tid; i < 24 * 72; i += 256) {
        int r = i / 72, c = i % 72;
        int gy = ty0 + r, gx = tx0 + c;
        s_in[r][c] = (gy >= 0 && gy < H && gx >= 0 && gx < W) ? inb[gy * W + gx] : 0.f;
    }
    __syncthreads();

    int oy  = blockIdx.y * 16 + threadIdx.y;
    int ox0 = blockIdx.x * 64 + threadIdx.x * 4;
    float* outb = g_h1 + (((size_t)z * 64) * H + oy) * W + ox0;

    for (int occ = 0; occ < 64; occ += 16) {
        float acc[16][4];
#pragma unroll
        for (int o = 0; o < 16; o++) {
            float bv = s_b[occ + o];
            acc[o][0] = bv; acc[o][1] = bv; acc[o][2] = bv; acc[o][3] = bv;
        }
#pragma unroll
        for (int ky = 0; ky < 9; ky++) {
            float r[12];
#pragma unroll
            for (int j = 0; j < 12; j++)
                r[j] = s_in[threadIdx.y + ky][threadIdx.x * 4 + j];
#pragma unroll
            for (int o = 0; o < 16; o++) {
                const float* wr = &s_w[(occ + o) * 81 + ky * 9];
#pragma unroll
                for (int kx = 0; kx < 9; kx++) {
                    float w = wr[kx];
                    acc[o][0] = fmaf(r[kx],     w, acc[o][0]);
                    acc[o][1] = fmaf(r[kx + 1], w, acc[o][1]);
                    acc[o][2] = fmaf(r[kx + 2], w, acc[o][2]);
                    acc[o][3] = fmaf(r[kx + 3], w, acc[o][3]);
                }
            }
        }
#pragma unroll
        for (int o = 0; o < 16; o++) {
            float4 v = make_float4(fmaxf(acc[o][0], 0.f), fmaxf(acc[o][1], 0.f),
                                   fmaxf(acc[o][2], 0.f), fmaxf(acc[o][3], 0.f));
            *reinterpret_cast<float4*>(outb + (size_t)(occ + o) * H * W) = v;
        }
    }
}

// ---------------------------------------------------------------------------
// h1 split/transpose: fp32 planar -> fp16 hi/lo pixel-major
// ---------------------------------------------------------------------------
__global__ __launch_bounds__(256) void h1_split_kernel(int HW)
{
    __shared__ float tile[64][65];
    int ub  = blockIdx.z;
    int px0 = blockIdx.x * 64;
    int t   = threadIdx.x;
    const float* src = g_h1 + (size_t)ub * 64 * HW;
#pragma unroll
    for (int k = 0; k < 16; k++) {
        int j = t + k * 256;
        int px = j & 63, ic = j >> 6;
        tile[ic][px] = src[(size_t)ic * HW + px0 + px];
    }
    __syncthreads();
    __half* dh = g_h1h + ((size_t)ub * HW + px0) * 64;
    __half* dl = g_h1l + ((size_t)ub * HW + px0) * 64;
#pragma unroll
    for (int k = 0; k < 4; k++) {
        int j = t + k * 256;
        int px = j >> 4, c = j & 15, ic0 = c * 4;
        __half hh[4], hl[4];
#pragma unroll
        for (int i = 0; i < 4; i++) {
            float f = tile[ic0 + i][px];
            __half h = __float2half_rn(f);
            hh[i] = h;
            hl[i] = __float2half_rn(f - __half2float(h));
        }
        *(uint2*)(dh + (size_t)px * 64 + ic0) = *(uint2*)hh;
        *(uint2*)(dl + (size_t)px * 64 + ic0) = *(uint2*)hl;
    }
}

// ---------------------------------------------------------------------------
// conv2 tensor-core (mma.sync): 64->32, 5x5, pad 2, ReLU.
// CTA 256 thr: warps 0-3 row y (x-tiles of 16), warps 4-7 row y+1.
// A: 6-row SMEM ring, 68 px * 144B pitch, hi+lo. dy,dx via shifted ldmatrix.
// B: fragment-order SMEM (LDS.64), 16 oc per CTA (grid.z = ub*2+ocg).
// 3 hi/lo products into separate fp32 accumulators.
// ---------------------------------------------------------------------------
__global__ __launch_bounds__(256, 1) void conv2_tc_kernel(
    const float* __restrict__ Wp, const float* __restrict__ Bp,
    int H, int W)
{
    extern __shared__ __align__(16) char smem[];
    uint32_t sb = smem_u32(smem);
    int tid = threadIdx.x, wid = tid >> 5, lane = tid & 31;
    int zz = blockIdx.z;
    int ocg = zz & 1, ub = zz >> 1, u = ub / BATCH;
    int oc0 = ocg * 16;
    int x0 = blockIdx.x * 64;
    int HW = H * W;
    int S = H >> 3;                    // rows per CTA (gridDim.y == 8)
    int ybase = blockIdx.y * S, yend = ybase + S;

    // ---- stage B fragments: 400 frags * 32 lanes ----
    const float* wub = Wp + (size_t)u * 32 * 1600;
    for (int j = tid; j < 12800; j += 256) {
        int t = j & 31, f = j >> 5;
        int prod = f & 1, n8 = (f >> 1) & 1, k = (f >> 2) & 3, tap = f >> 4;
        int col = t >> 2, icb = k * 16 + (t & 3) * 2;
        int oc = oc0 + n8 * 8 + col;
        const float* wp = wub + (size_t)(oc) * 1600 + tap;   // tap = dy*5+dx
        float w0 = wp[(icb + 0) * 25], w1 = wp[(icb + 1) * 25];
        float w2 = wp[(icb + 8) * 25], w3 = wp[(icb + 9) * 25];
        __half h0 = __float2half_rn(w0), h1 = __float2half_rn(w1);
        __half h2 = __float2half_rn(w2), h3 = __float2half_rn(w3);
        if (prod) {     // lo residuals
            h0 = __float2half_rn(w0 - __half2float(h0));
            h1 = __float2half_rn(w1 - __half2float(h1));
            h2 = __float2half_rn(w2 - __half2float(h2));
            h3 = __float2half_rn(w3 - __half2float(h3));
        }
        __half hp[4] = { h0, h1, h2, h3 };
        *(uint2*)(smem + B_OFF + f * 256 + t * 8) = *(uint2*)hp;
    }

    const __half* h1h = g_h1h + (size_t)ub * HW * 64;
    const __half* h1l = g_h1l + (size_t)ub * HW * 64;

    // ---- stage rows [r0, r0+nrows) into ring ----
    auto stage = [&](int r0, int nrows) {
        int total = nrows * 2 * 68 * 8;
        for (int j = tid; j < total; j += 256) {
            int ic4 = j & 7;
            int t2 = j >> 3;
            int px = t2 % 68;
            int pl = t2 / 68;
            int row = pl >> 1, half = pl & 1;
            int r = r0 + row;
            int x = x0 - 2 + px;
            uint4 v = make_uint4(0, 0, 0, 0);
            if (r >= 0 && r < H && x >= 0 && x < W) {
                const __half* s = half ? h1l : h1h;
                v = *(const uint4*)(s + ((size_t)r * W + x) * 64 + ic4 * 8);
            }
            uint32_t off = (half ? A_LO : A_HI)
                         + (uint32_t)(((r + 6) % 6)) * SLOT_B + px * 144 + ic4 * 16;
            *(uint4*)(smem + off) = v;
        }
    };

    stage(ybase - 2, 6);
    __syncthreads();

    int ygrp = wid >> 2, wx = wid & 3;
    int lane15 = lane & 15, kadd = (lane >> 4) * 16;

    for (int y = ybase; y < yend; y += 2) {
        int y_out = y + ygrp;
        float c[2][3][4];
#pragma unroll
        for (int n8 = 0; n8 < 2; n8++)
#pragma unroll
            for (int p = 0; p < 3; p++)
#pragma unroll
                for (int i = 0; i < 4; i++) c[n8][p][i] = 0.f;

        for (int dy = 0; dy < 5; dy++) {
            int ra = y_out + dy - 2;
            uint32_t rbH = sb + A_HI + (uint32_t)((ra + 6) % 6) * SLOT_B;
            uint32_t rbL = rbH + A_LO;
            for (int dx = 0; dx < 5; dx++) {
                uint32_t arow = (uint32_t)(wx * 16 + dx + lane15) * 144 + kadd;
                uint32_t fbase = sb + B_OFF + (uint32_t)(dy * 5 + dx) * 16 * 256 + lane * 8;
#pragma unroll
                for (int k = 0; k < 4; k++) {
                    uint32_t ah[4], al[4];
                    ldmat4(ah, rbH + arow + k * 32);
                    ldmat4(al, rbL + arow + k * 32);
#pragma unroll
                    for (int n8 = 0; n8 < 2; n8++) {
                        uint32_t fo = fbase + (uint32_t)(k * 4 + n8 * 2) * 256;
                        uint32_t bh0, bh1, bl0, bl1;
                        asm volatile("ld.shared.v2.b32 {%0,%1}, [%2];"
                                     : "=r"(bh0), "=r"(bh1) : "r"(fo));
                        asm volatile("ld.shared.v2.b32 {%0,%1}, [%2];"
                                     : "=r"(bl0), "=r"(bl1) : "r"(fo + 256));
                        mma16816(c[n8][0], ah, bh0, bh1);
                        mma16816(c[n8][1], ah, bl0, bl1);
                        mma16816(c[n8][2], al, bh0, bh1);
                    }
                }
            }
        }

        // epilogue
        int px = lane >> 2, colp = (lane & 3) * 2;
#pragma unroll
        for (int n8 = 0; n8 < 2; n8++) {
            int ocl = oc0 + n8 * 8 + colp;
            float b0v = __ldg(Bp + u * 32 + ocl);
            float b1v = __ldg(Bp + u * 32 + ocl + 1);
            float s0 = c[n8][0][0] + c[n8][1][0] + c[n8][2][0] + b0v;
            float s1 = c[n8][0][1] + c[n8][1][1] + c[n8][2][1] + b1v;
            float s2 = c[n8][0][2] + c[n8][1][2] + c[n8][2][2] + b0v;
            float s3 = c[n8][0][3] + c[n8][1][3] + c[n8][2][3] + b1v;
            float* base = g_h2 + ((size_t)ub * 32 + ocl) * HW
                        + (size_t)y_out * W + x0 + wx * 16;
            base[px]          = fmaxf(s0, 0.f);
            base[HW + px]     = fmaxf(s1, 0.f);
            base[px + 8]      = fmaxf(s2, 0.f);
            base[HW + px + 8] = fmaxf(s3, 0.f);
        }
        __syncthreads();
        if (y + 2 < yend) {
            stage(y + 4, 2);
            __syncthreads();
        }
    }
}

// ---------------------------------------------------------------------------
// conv3: 32 -> 1, 5x5, pad 2, no ReLU, writes (optionally interleaved) output.
// ---------------------------------------------------------------------------
__global__ __launch_bounds__(256) void conv3_kernel(
    const float* __restrict__ Wp, const float* __restrict__ Bp,
    float* __restrict__ outsec, int H, int W, int interleave)
{
    __shared__ float s_in[36][36];
    __shared__ float s_w[25];

    int z = blockIdx.z;
    int u = z / BATCH, b = z % BATCH;
    int tid = threadIdx.y * 16 + threadIdx.x;

    const float* wbase = Wp + (size_t)u * 32 * 25;
    float bv = Bp[u];
    float a00 = bv, a01 = bv, a10 = bv, a11 = bv;

    int ty0 = blockIdx.y * 32 - 2, tx0 = blockIdx.x * 32 - 2;
    const float* h2b = g_h2 + ((size_t)z * 32) * H * W;
    int iy = threadIdx.y * 2, ix = threadIdx.x * 2;

    for (int ic = 0; ic < 32; ic++) {
        __syncthreads();
        const float* inc = h2b + (size_t)ic * H * W;
        for (int i = tid; i < 36 * 36; i += 256) {
            int r = i / 36, c = i % 36;
            int gy = ty0 + r, gx = tx0 + c;
            s_in[r][c] = (gy >= 0 && gy < H && gx >= 0 && gx < W) ? inc[gy * W + gx] : 0.f;
        }
        if (tid < 25) s_w[tid] = wbase[ic * 25 + tid];
        __syncthreads();

#pragma unroll
        for (int ky = 0; ky < 5; ky++) {
            float rA[6], rB[6];
#pragma unroll
            for (int j = 0; j < 6; j++) {
                rA[j] = s_in[iy + ky][ix + j];
                rB[j] = s_in[iy + ky + 1][ix + j];
            }
#pragma unroll
            for (int kx = 0; kx < 5; kx++) {
                float w = s_w[ky * 5 + kx];
                a00 = fmaf(rA[kx],     w, a00);
                a01 = fmaf(rA[kx + 1], w, a01);
                a10 = fmaf(rB[kx],     w, a10);
                a11 = fmaf(rB[kx + 1], w, a11);
            }
        }
    }

    int oy = blockIdx.y * 32 + iy, ox = blockIdx.x * 32 + ix;
    int s  = interleave ? 2 : 1;
    int ry = interleave ? (u >> 1) : 0;
    int rx = interleave ? (u & 1) : 0;
    int OW = s * W, OH = s * H;
    float* ob = outsec + (size_t)b * OH * OW;
    ob[(size_t)(s * oy + ry)       * OW + s * ox       + rx] = a00;
    ob[(size_t)(s * oy + ry)       * OW + s * (ox + 1) + rx] = a01;
    ob[(size_t)(s * (oy + 1) + ry) * OW + s * ox       + rx] = a10;
    ob[(size_t)(s * (oy + 1) + ry) * OW + s * (ox + 1) + rx] = a11;
}

// ---------------------------------------------------------------------------
__device__ __forceinline__ float bil_up(const float* img, int N, int sc, int y, int x)
{
    float fy = (y + 0.5f) / sc - 0.5f;
    float fx = (x + 0.5f) / sc - 0.5f;
    int y0 = (int)floorf(fy); float wy = fy - y0;
    int x0 = (int)floorf(fx); float wx = fx - x0;
    int y0c = y0 < 0 ? 0 : y0;  int y1c = y0 + 1 > N - 1 ? N - 1 : y0 + 1;
    int x0c = x0 < 0 ? 0 : x0;  int x1c = x0 + 1 > N - 1 ? N - 1 : x0 + 1;
    float p00 = img[(size_t)y0c * N + x0c], p01 = img[(size_t)y0c * N + x1c];
    float p10 = img[(size_t)y1c * N + x0c], p11 = img[(size_t)y1c * N + x1c];
    return (1.f - wy) * ((1.f - wx) * p00 + wx * p01)
         +        wy  * ((1.f - wx) * p10 + wx * p11);
}

__global__ __launch_bounds__(256) void msf_in_kernel(const float* __restrict__ outbuf)
{
    int idx = blockIdx.x * blockDim.x + threadIdx.x;
    if (idx >= BATCH * 512 * 512) return;
    int x = idx & 511;
    int y = (idx >> 9) & 511;
    int b = idx >> 18;
    const float* x2 = outbuf + 0      + (size_t)b * 128 * 128;
    const float* x4 = outbuf + 65536  + (size_t)b * 256 * 256;
    const float* x8 = outbuf + 327680 + (size_t)b * 512 * 512;
    g_msf[idx] = bil_up(x2, 128, 4, y, x)
               + bil_up(x4, 256, 2, y, x)
               + x8[(size_t)y * 512 + x];
}

// ---------------------------------------------------------------------------
extern "C" void kernel_launch(void* const* d_in, const int* in_sizes, int n_in,
                              void* d_out, int out_size)
{
    const float* image = (const float*)d_in[0];
    const float* W1 = (const float*)d_in[1];
    const float* B1 = (const float*)d_in[2];
    const float* W2 = (const float*)d_in[3];
    const float* B2 = (const float*)d_in[4];
    const float* W3 = (const float*)d_in[5];
    const float* B3 = (const float*)d_in[6];
    float* out = (float*)d_out;

    static int smem_set = 0;
    if (!smem_set) {
        cudaFuncSetAttribute(conv2_tc_kernel,
                             cudaFuncAttributeMaxDynamicSharedMemorySize, C2_SMEM);
        smem_set = 1;
    }

    float* sec_x2  = out;
    float* sec_x4  = out + 65536;
    float* sec_x8  = out + 327680;
    float* sec_msf = out + 1376256;

    struct Stage { const float* in; int use_msf, H, W, ub, U, inter; float* osec; };
    Stage st[4] = {
        { image,   0,  64,  64,  0, 4, 1, sec_x2  },
        { sec_x2,  0, 128, 128,  4, 4, 1, sec_x4  },
        { sec_x4,  0, 256, 256,  8, 4, 1, sec_x8  },
        { nullptr, 1, 512, 512, 12, 1, 0, sec_msf },
    };

    dim3 blk(16, 16);
    for (int s = 0; s < 4; s++) {
        if (s == 3)
            msf_in_kernel<<<(BATCH * 512 * 512 + 255) / 256, 256>>>(out);
        Stage& t = st[s];
        int UB = t.U * BATCH, HW = t.H * t.W;
        conv1_kernel<<<dim3(t.W / 64, t.H / 16, UB), blk>>>(
            t.in, t.use_msf,
            W1 + (size_t)t.ub * 64 * 81, B1 + (size_t)t.ub * 64, t.H, t.W);
        h1_split_kernel<<<dim3(HW / 64, 1, UB), 256>>>(HW);
        conv2_tc_kernel<<<dim3(t.W / 64, 8, UB * 2), 256, C2_SMEM>>>(
            W2 + (size_t)t.ub * 32 * 64 * 25, B2 + (size_t)t.ub * 32, t.H, t.W);
        conv3_kernel<<<dim3(t.W / 32, t.H / 32, UB), blk>>>(
            W3 + (size_t)t.ub * 32 * 25, B3 + t.ub, t.osec, t.H, t.W, t.inter);
    }
}